// round 15
// baseline (speedup 1.0000x reference)
#include <cuda_runtime.h>
#include <cuda_fp16.h>
#include <math.h>

#define NN 50000
#define NE 600000
#define DD 128
#define NL 4
#define NG 512
#define NT 10
#define EPSF 1e-5f

// ---------------- scratch (static device allocations) ----------------
__device__ int   g_deg[NN];
__device__ int   g_rowptr[NN + 1];
__device__ int   g_cursor[NN];
__device__ int   g_srcperm[NE];
__device__ float g_amp[NN], g_att[NN], g_dinv[NN];
__device__ float g_delta_acc;
__device__ float g_h[NN * DD];
__device__ unsigned g_hH[NN * DD / 2];              // fp16 mirror of g_h (packed half2)
__device__ unsigned g_aggsH[(size_t)NN * 256];      // [N][512] halves: unscaled mean|min|max|std
__device__ float g_out[NN * DD];
__device__ float g_bnsum[DD], g_bnsq[DD];
__device__ int   g_gcnt[NG];
__device__ int   g_goff[NG + 1];
__device__ __half g_WtH[(size_t)NL * DD * 1536];    // W transposed fp16: [l][n][k]

// ---------------- small helpers ----------------
__device__ __forceinline__ float4 f4zero() { return make_float4(0.f, 0.f, 0.f, 0.f); }

__device__ __forceinline__ unsigned packh2(float a, float b) {
    __half2 h = __floats2half2_rn(a, b);
    return *(unsigned*)&h;
}
__device__ __forceinline__ unsigned hmul2u(unsigned a, unsigned s) {
    __half2 r = __hmul2(*(__half2*)&a, *(__half2*)&s);
    return *(unsigned*)&r;
}

__device__ __forceinline__ void cp_async16(unsigned smem_addr, const void* gptr) {
    asm volatile("cp.async.cg.shared.global [%0], [%1], 16;" :: "r"(smem_addr), "l"(gptr));
}
__device__ __forceinline__ void cp_async16p(unsigned smem_addr, const void* gptr, int szbytes) {
    asm volatile("cp.async.cg.shared.global [%0], [%1], 16, %2;"
                 :: "r"(smem_addr), "l"(gptr), "r"(szbytes));
}
__device__ __forceinline__ void cp_commit() { asm volatile("cp.async.commit_group;"); }
__device__ __forceinline__ void cp_wait0() { asm volatile("cp.async.wait_group 0;"); }

__device__ __forceinline__ void ldsm_x4(unsigned& r0, unsigned& r1, unsigned& r2, unsigned& r3,
                                        unsigned addr) {
    asm volatile("ldmatrix.sync.aligned.m8n8.x4.shared.b16 {%0,%1,%2,%3}, [%4];"
                 : "=r"(r0), "=r"(r1), "=r"(r2), "=r"(r3) : "r"(addr));
}

#define MMA16816(acc, a0, a1, a2, a3, b0, b1) \
    asm volatile( \
        "mma.sync.aligned.m16n8k16.row.col.f32.f16.f16.f32 " \
        "{%0,%1,%2,%3}, {%4,%5,%6,%7}, {%8,%9}, {%0,%1,%2,%3};" \
        : "+f"((acc)[0]), "+f"((acc)[1]), "+f"((acc)[2]), "+f"((acc)[3]) \
        : "r"(a0), "r"(a1), "r"(a2), "r"(a3), "r"(b0), "r"(b1))

// ---------------- setup kernels ----------------
__global__ void k_zero() {
    int i = blockIdx.x * blockDim.x + threadIdx.x;
    if (i < NN) { g_deg[i] = 0; g_cursor[i] = 0; }
    if (i < NG) g_gcnt[i] = 0;
    if (i == 0) g_delta_acc = 0.f;
}

__global__ void k_hist(const int* __restrict__ ei, const int* __restrict__ batch) {
    int e = blockIdx.x * blockDim.x + threadIdx.x;
    if (e < NE) atomicAdd(&g_deg[ei[NE + e]], 1);     // dst row
    if (e < NN) atomicAdd(&g_gcnt[batch[e]], 1);
}

// scans rowptr + graph offsets; also computes delta (sum of log1p(deg))
__global__ void k_scan() {
    __shared__ int s[1024];
    __shared__ float fs[1024];
    int t = threadIdx.x;
    const int C = (NN + 1023) / 1024;
    int base = t * C;
    int acc = 0;
    float dl = 0.f;
    for (int c = 0; c < C; c++) {
        int i = base + c;
        if (i < NN) { int d = g_deg[i]; acc += d; dl += log1pf((float)d); }
    }
    s[t] = acc;
    fs[t] = dl;
    __syncthreads();
    for (int d = 1; d < 1024; d <<= 1) {
        int add = (t >= d) ? s[t - d] : 0;
        __syncthreads();
        s[t] += add;
        __syncthreads();
    }
    int off = s[t] - acc;
    for (int c = 0; c < C; c++) { int i = base + c; if (i < NN) { g_rowptr[i] = off; off += g_deg[i]; } }
    if (t == 0) g_rowptr[NN] = NE;
    // delta reduce
    for (int d = 512; d; d >>= 1) {
        __syncthreads();
        if (t < d) fs[t] += fs[t + d];
    }
    if (t == 0) g_delta_acc = fs[0];
    __syncthreads();
    int v = (t < NG) ? g_gcnt[t] : 0;
    s[t] = v;
    __syncthreads();
    for (int d = 1; d < 1024; d <<= 1) {
        int add = (t >= d) ? s[t - d] : 0;
        __syncthreads();
        s[t] += add;
        __syncthreads();
    }
    if (t < NG) g_goff[t] = s[t] - v;
    if (t == 0) g_goff[NG] = NN;
}

// scatter edges to CSR + per-node scalars (amp/att/dinv)
__global__ void k_scatter(const int* __restrict__ ei) {
    int e = blockIdx.x * blockDim.x + threadIdx.x;
    if (e < NN) {
        float deg = (float)g_deg[e];
        float d = fmaxf(deg, 1.f);
        float ld = log1pf(d);
        float delta = g_delta_acc / (float)NN;
        g_amp[e] = ld / delta;
        g_att[e] = delta / ld;
        g_dinv[e] = 1.f / d;
    }
    if (e >= NE) return;
    int dst = ei[NE + e];
    int p = atomicAdd(&g_cursor[dst], 1);
    g_srcperm[g_rowptr[dst] + p] = ei[e];
}

// merged: node embedding + weight transpose/convert
__global__ void k_prep(const float* __restrict__ x, const float* __restrict__ W,
                       const float* __restrict__ b, const float* __restrict__ conv_W) {
    int t = blockIdx.x * blockDim.x + threadIdx.x;
    if (t < NN * 32) {
        int i = t >> 5, c = t & 31;
        float x0 = x[i * 3 + 0], x1 = x[i * 3 + 1], x2 = x[i * 3 + 2];
        float4 w0 = *(const float4*)&W[0 * DD + c * 4];
        float4 w1 = *(const float4*)&W[1 * DD + c * 4];
        float4 w2 = *(const float4*)&W[2 * DD + c * 4];
        float4 bb = *(const float4*)&b[c * 4];
        float4 h;
        h.x = bb.x + x0 * w0.x + x1 * w1.x + x2 * w2.x;
        h.y = bb.y + x0 * w0.y + x1 * w1.y + x2 * w2.y;
        h.z = bb.z + x0 * w0.z + x1 * w1.z + x2 * w2.z;
        h.w = bb.w + x0 * w0.w + x1 * w1.w + x2 * w2.w;
        ((float4*)g_h)[i * 32 + c] = h;
        ((uint2*)g_hH)[i * 32 + c] = make_uint2(packh2(h.x, h.y), packh2(h.z, h.w));
    }
    if (t < NL * 1536 * DD) {
        int l = t / (1536 * DD);
        int r = t - l * (1536 * DD);
        int k = r >> 7;
        int n = r & 127;
        g_WtH[((size_t)l * DD + n) * 1536 + k] = __float2half_rn(conv_W[t]);
    }
}

// ---------------- per-layer kernels ----------------
// TWO nodes per warp (16-lane segments, uint4 = 8 channels/lane).
__global__ void k_agg() {
    if (blockIdx.x == 0 && threadIdx.x < DD) {    // reset BN accumulators for this layer
        g_bnsum[threadIdx.x] = 0.f;
        g_bnsq[threadIdx.x] = 0.f;
    }
    int warp = (blockIdx.x * blockDim.x + threadIdx.x) >> 5;
    int lane = threadIdx.x & 31;
    int sl = lane & 15;
    int node = warp * 2 + (lane >> 4);
    if (warp * 2 >= NN) return;
    bool ok = node < NN;
    int beg = ok ? g_rowptr[node] : 0;
    int end = ok ? g_rowptr[node + 1] : 0;
    int deg = end - beg;
    int odeg = __shfl_xor_sync(0xffffffffu, deg, 16);
    int maxdeg = max(deg, odeg);

    float s1[8], s2[8], mn[8], mx[8];
#pragma unroll
    for (int c = 0; c < 8; c++) { s1[c] = 0.f; s2[c] = 0.f; mn[c] = INFINITY; mx[c] = -INFINITY; }

    const uint4* hp = (const uint4*)g_hH;    // 16 uint4 per node row
    for (int e0 = 0; e0 < maxdeg; e0 += 16) {
        int myE = beg + e0 + sl;
        int myj = (myE < end) ? g_srcperm[myE] : 0;
        int cnt = deg - e0;                  // per-segment remaining
#pragma unroll
        for (int kk = 0; kk < 16; kk++) {
            int j = __shfl_sync(0xffffffffu, myj, (lane & 16) + kk);
            if (kk < cnt) {
                uint4 v = hp[j * 16 + sl];
                float2 f0 = __half22float2(*(__half2*)&v.x);
                float2 f1 = __half22float2(*(__half2*)&v.y);
                float2 f2 = __half22float2(*(__half2*)&v.z);
                float2 f3 = __half22float2(*(__half2*)&v.w);
                float m[8] = { f0.x, f0.y, f1.x, f1.y, f2.x, f2.y, f3.x, f3.y };
#pragma unroll
                for (int c = 0; c < 8; c++) {
                    s1[c] += m[c];
                    s2[c] += m[c] * m[c];
                    mn[c] = fminf(mn[c], m[c]);
                    mx[c] = fmaxf(mx[c], m[c]);
                }
            }
        }
    }
    if (!ok) return;
    float dinv = g_dinv[node];
    float mean[8], sd[8];
#pragma unroll
    for (int c = 0; c < 8; c++) {
        mean[c] = s1[c] * dinv;
        sd[c] = sqrtf(fmaxf(s2[c] * dinv - mean[c] * mean[c], 0.f) + EPSF);
        if (deg == 0) { mn[c] = 0.f; mx[c] = 0.f; }
    }
    unsigned* base = g_aggsH + (size_t)node * 256;
    uint4 w;
    w.x = packh2(mean[0], mean[1]); w.y = packh2(mean[2], mean[3]);
    w.z = packh2(mean[4], mean[5]); w.w = packh2(mean[6], mean[7]);
    *(uint4*)&base[0 * 64 + sl * 4] = w;
    w.x = packh2(mn[0], mn[1]); w.y = packh2(mn[2], mn[3]);
    w.z = packh2(mn[4], mn[5]); w.w = packh2(mn[6], mn[7]);
    *(uint4*)&base[1 * 64 + sl * 4] = w;
    w.x = packh2(mx[0], mx[1]); w.y = packh2(mx[2], mx[3]);
    w.z = packh2(mx[4], mx[5]); w.w = packh2(mx[6], mx[7]);
    *(uint4*)&base[2 * 64 + sl * 4] = w;
    w.x = packh2(sd[0], sd[1]); w.y = packh2(sd[2], sd[3]);
    w.z = packh2(sd[4], sd[5]); w.w = packh2(sd[6], sd[7]);
    *(uint4*)&base[3 * 64 + sl * 4] = w;
}

// ---------------- FP16 tensor-core GEMM with in-fragment slab scaling ----------------
// out = Σ_s (scale_s ⊙ A) @ W_s.  16 chunks of K=32; per chunk: 1 A tile + 3 B tiles.
#define BM 128
#define SW 20                          // 32-bit words per row (16 used + 4 pad)
#define NCH3 16                        // 512 / 32
#define TILE_B (BM * SW * 4)           // 10240 bytes per tile
#define STAGE_B (4 * TILE_B)           // A + 3 B
#define GM_DYN (2 * STAGE_B)           // 81920

__global__ __launch_bounds__(256, 2) void k_gemm(const __half* __restrict__ WtH,
                                                 const float* __restrict__ bl) {
    extern __shared__ unsigned dynS[];
    __shared__ float sBias[DD];
    __shared__ float sSum[DD], sSq[DD];
    __shared__ unsigned sAmp2[BM], sAtt2[BM];   // half2 broadcast per row

    int bm = blockIdx.x * BM;
    int tid = threadIdx.x;
    int lane = tid & 31;
    int warp = tid >> 5;
    int g = lane >> 2;
    int t = lane & 3;
    int m_base = (warp >> 2) * 64;
    int n_base = (warp & 3) * 32;

    if (tid < DD) {
        sBias[tid] = bl[tid];
        sSum[tid] = 0.f;
        sSq[tid] = 0.f;
        int r = bm + tid;
        float af = (r < NN) ? g_amp[r] : 1.f;
        float tf = (r < NN) ? g_att[r] : 1.f;
        sAmp2[tid] = packh2(af, af);
        sAtt2[tid] = packh2(tf, tf);
    }
    __syncthreads();

    float acc[4][4][4];
#pragma unroll
    for (int i = 0; i < 4; i++)
#pragma unroll
        for (int j = 0; j < 4; j++)
#pragma unroll
            for (int c = 0; c < 4; c++) acc[i][j][c] = 0.f;

    const int cpRow = tid >> 2;
    const int cpSeg = tid & 3;
    const int row2 = cpRow + 64;

    const unsigned base = (unsigned)__cvta_generic_to_shared(&dynS[0]);

    auto cpAB = [&](int chunk, int buf) {
        unsigned st = base + buf * STAGE_B;
#pragma unroll
        for (int u = 0; u < 2; u++) {
            int row = u ? row2 : cpRow;
            unsigned dst = (unsigned)(row * SW + cpSeg * 4) * 4u;
            const unsigned* pa = g_aggsH + (size_t)(bm + row) * 256 + chunk * 16 + cpSeg * 4;
            cp_async16p(st + dst, pa, (bm + row) < NN ? 16 : 0);
#pragma unroll
            for (int s = 0; s < 3; s++)
                cp_async16(st + (1 + s) * TILE_B + dst,
                           WtH + (size_t)row * 1536 + s * 512 + chunk * 32 + cpSeg * 8);
        }
    };

    const int l8 = lane & 7;
    const unsigned aLane = (unsigned)((l8 + ((lane >> 3) & 1) * 8) * SW * 4 + ((lane >> 4) & 1) * 16);
    const unsigned bLane = (unsigned)((l8 + ((lane >> 4) & 1) * 8) * SW * 4 + ((lane >> 3) & 1) * 16);

    auto mmaChunk = [&](int buf) {
        unsigned st = base + buf * STAGE_B;
        unsigned aB = st + (unsigned)(m_base * SW * 4) + aLane;
        unsigned bB = st + TILE_B + (unsigned)(n_base * SW * 4) + bLane;
#pragma unroll
        for (int ks = 0; ks < 2; ks++) {
            unsigned bf[3][4][2];
#pragma unroll
            for (int s = 0; s < 3; s++) {
                unsigned bb = bB + s * TILE_B;
                ldsm_x4(bf[s][0][0], bf[s][0][1], bf[s][1][0], bf[s][1][1], bb + ks * 32);
                ldsm_x4(bf[s][2][0], bf[s][2][1], bf[s][3][0], bf[s][3][1], bb + 16 * SW * 4 + ks * 32);
            }
#pragma unroll
            for (int i = 0; i < 4; i++) {
                unsigned a0, a1, a2, a3;
                ldsm_x4(a0, a1, a2, a3, aB + (unsigned)(i * 16 * SW * 4) + ks * 32);
#pragma unroll
                for (int j = 0; j < 4; j++)
                    MMA16816(acc[i][j], a0, a1, a2, a3, bf[0][j][0], bf[0][j][1]);
                int rl = m_base + i * 16 + g;
                {
                    unsigned sl = sAmp2[rl], sh = sAmp2[rl + 8];
                    unsigned u0 = hmul2u(a0, sl), u1 = hmul2u(a1, sh);
                    unsigned u2 = hmul2u(a2, sl), u3 = hmul2u(a3, sh);
#pragma unroll
                    for (int j = 0; j < 4; j++)
                        MMA16816(acc[i][j], u0, u1, u2, u3, bf[1][j][0], bf[1][j][1]);
                }
                {
                    unsigned sl = sAtt2[rl], sh = sAtt2[rl + 8];
                    unsigned u0 = hmul2u(a0, sl), u1 = hmul2u(a1, sh);
                    unsigned u2 = hmul2u(a2, sl), u3 = hmul2u(a3, sh);
#pragma unroll
                    for (int j = 0; j < 4; j++)
                        MMA16816(acc[i][j], u0, u1, u2, u3, bf[2][j][0], bf[2][j][1]);
                }
            }
        }
    };

    cpAB(0, 0);
    cp_commit();

    for (int c = 0; c < NCH3; c++) {
        cp_wait0();
        __syncthreads();
        if (c + 1 < NCH3) {
            cpAB(c + 1, (c + 1) & 1);
            cp_commit();
        }
        mmaChunk(c & 1);
    }

    // epilogue: bias + store
#pragma unroll
    for (int i = 0; i < 4; i++) {
        int r0 = bm + m_base + i * 16 + g;
        int r1 = r0 + 8;
#pragma unroll
        for (int j = 0; j < 4; j++) {
            int col = n_base + j * 8 + t * 2;
            float bx = sBias[col], by = sBias[col + 1];
            acc[i][j][0] += bx; acc[i][j][1] += by;
            acc[i][j][2] += bx; acc[i][j][3] += by;
            if (r0 < NN)
                *(float2*)&g_out[(size_t)r0 * DD + col] = make_float2(acc[i][j][0], acc[i][j][1]);
            if (r1 < NN)
                *(float2*)&g_out[(size_t)r1 * DD + col] = make_float2(acc[i][j][2], acc[i][j][3]);
        }
    }

    // fused BN stats
#pragma unroll
    for (int j = 0; j < 4; j++)
#pragma unroll
        for (int c2 = 0; c2 < 2; c2++) {
            int col = n_base + j * 8 + t * 2 + c2;
            float s = 0.f, q = 0.f;
#pragma unroll
            for (int i = 0; i < 4; i++) {
                int r0 = bm + m_base + i * 16 + g;
                float v0 = acc[i][j][c2];
                float v1 = acc[i][j][2 + c2];
                if (r0 < NN) { s += v0; q += v0 * v0; }
                if (r0 + 8 < NN) { s += v1; q += v1 * v1; }
            }
#pragma unroll
            for (int m = 4; m <= 16; m <<= 1) {
                s += __shfl_xor_sync(0xffffffffu, s, m);
                q += __shfl_xor_sync(0xffffffffu, q, m);
            }
            if (g == 0) {
                atomicAdd(&sSum[col], s);
                atomicAdd(&sSq[col], q);
            }
        }
    __syncthreads();
    if (tid < DD) {
        atomicAdd(&g_bnsum[tid], sSum[tid]);
        atomicAdd(&g_bnsq[tid], sSq[tid]);
    }
}

// BN apply with inline param computation + residual; optional fp16 mirror
__global__ void k_bnapply(const float* __restrict__ gamma, const float* __restrict__ beta,
                          int mirror) {
    int t = blockIdx.x * blockDim.x + threadIdx.x;
    if (t >= NN * 32) return;
    int c = (t & 31) * 4;
    float mu[4], rsg[4], bt[4];
#pragma unroll
    for (int u = 0; u < 4; u++) {
        float m = g_bnsum[c + u] / (float)NN;
        float var = g_bnsq[c + u] / (float)NN - m * m;
        mu[u] = m;
        rsg[u] = rsqrtf(var + EPSF) * gamma[c + u];
        bt[u] = beta[c + u];
    }
    float4 o = ((const float4*)g_out)[t];
    float4 h = ((float4*)g_h)[t];
    o.x = fmaxf((o.x - mu[0]) * rsg[0] + bt[0], 0.f) + h.x;
    o.y = fmaxf((o.y - mu[1]) * rsg[1] + bt[1], 0.f) + h.y;
    o.z = fmaxf((o.z - mu[2]) * rsg[2] + bt[2], 0.f) + h.z;
    o.w = fmaxf((o.w - mu[3]) * rsg[3] + bt[3], 0.f) + h.w;
    ((float4*)g_h)[t] = o;
    if (mirror)
        ((uint2*)g_hH)[t] = make_uint2(packh2(o.x, o.y), packh2(o.z, o.w));
}

// ---------------- fused pooling + MLP: one block per graph ----------------
__global__ void k_poolmlp(const float* __restrict__ W1, const float* __restrict__ b1,
                          const float* __restrict__ W2, const float* __restrict__ b2,
                          const float* __restrict__ W3, const float* __restrict__ b3,
                          float* __restrict__ out) {
    __shared__ float sg[DD], sz1[64], sz2[32];
    int gid = blockIdx.x;
    int tid = threadIdx.x;      // 128 threads, one per feature
    int beg = g_goff[gid], end = g_goff[gid + 1];
    float s = 0.f;
    for (int r = beg; r < end; r++) s += g_h[(size_t)r * DD + tid];
    sg[tid] = s / (float)max(end - beg, 1);
    __syncthreads();
    if (tid < 64) {
        float a = b1[tid];
        for (int k = 0; k < DD; k++) a += sg[k] * W1[k * 64 + tid];
        sz1[tid] = fmaxf(a, 0.f);
    }
    __syncthreads();
    if (tid < 32) {
        float a = b2[tid];
        for (int k = 0; k < 64; k++) a += sz1[k] * W2[k * 32 + tid];
        sz2[tid] = fmaxf(a, 0.f);
    }
    __syncthreads();
    if (tid < NT) {
        float a = b3[tid];
        for (int k = 0; k < 32; k++) a += sz2[k] * W3[k * NT + tid];
        out[gid * NT + tid] = a;
    }
}

// ---------------- launch ----------------
extern "C" void kernel_launch(void* const* d_in, const int* in_sizes, int n_in,
                              void* d_out, int out_size) {
    const float* x      = (const float*)d_in[0];
    const int*   ei     = (const int*)d_in[1];
    const int*   batch  = (const int*)d_in[2];
    const float* emb_W  = (const float*)d_in[3];
    const float* emb_b  = (const float*)d_in[4];
    const float* conv_W = (const float*)d_in[5];
    const float* conv_b = (const float*)d_in[6];
    const float* bng    = (const float*)d_in[7];
    const float* bnb    = (const float*)d_in[8];
    const float* W1     = (const float*)d_in[9];
    const float* b1     = (const float*)d_in[10];
    const float* W2     = (const float*)d_in[11];
    const float* b2     = (const float*)d_in[12];
    const float* W3     = (const float*)d_in[13];
    const float* b3     = (const float*)d_in[14];
    float* out = (float*)d_out;

    cudaFuncSetAttribute(k_gemm, cudaFuncAttributeMaxDynamicSharedMemorySize, GM_DYN);

    k_zero<<<(NN + 255) / 256, 256>>>();
    k_hist<<<(NE + 255) / 256, 256>>>(ei, batch);
    k_scan<<<1, 1024>>>();
    k_scatter<<<(NE + 255) / 256, 256>>>(ei);
    k_prep<<<(NN * 32 + 255) / 256, 256>>>(x, emb_W, emb_b, conv_W);

    __half* g_WtH_ptr;
    cudaGetSymbolAddress((void**)&g_WtH_ptr, g_WtH);

    for (int l = 0; l < NL; l++) {
        k_agg<<<(NN / 2 * 32 + 255) / 256, 256>>>();
        k_gemm<<<(NN + BM - 1) / BM, 256, GM_DYN>>>(g_WtH_ptr + (size_t)l * DD * 1536,
                                                    conv_b + (size_t)l * DD);
        k_bnapply<<<(NN * 32 + 255) / 256, 256>>>(bng + (size_t)l * DD, bnb + (size_t)l * DD,
                                                  l < NL - 1);
    }

    k_poolmlp<<<NG, DD>>>(W1, b1, W2, b2, W3, b3, out);
}

// round 16
// speedup vs baseline: 1.0614x; 1.0614x over previous
#include <cuda_runtime.h>
#include <cuda_fp16.h>
#include <math.h>

#define NN 50000
#define NE 600000
#define DD 128
#define NL 4
#define NG 512
#define NT 10
#define EPSF 1e-5f

// ---------------- scratch (static device allocations) ----------------
__device__ int   g_deg[NN];
__device__ int   g_rowptr[NN + 1];
__device__ int   g_cursor[NN];
__device__ int   g_srcperm[NE];
__device__ float g_amp[NN], g_att[NN], g_dinv[NN];
__device__ float g_delta_acc;
__device__ float g_h[NN * DD];
__device__ unsigned g_hH[NN * DD / 2];              // fp16 mirror of g_h (packed half2)
__device__ unsigned g_aggsH[(size_t)NN * 256];      // [N][512] halves: unscaled mean|min|max|std
__device__ float g_out[NN * DD];
__device__ float g_bnsum[DD], g_bnsq[DD];
__device__ int   g_gcnt[NG];
__device__ int   g_goff[NG + 1];
__device__ __half g_WtH[(size_t)NL * DD * 1536];    // W transposed fp16: [l][n][k]

// ---------------- small helpers ----------------
__device__ __forceinline__ float4 f4zero() { return make_float4(0.f, 0.f, 0.f, 0.f); }

__device__ __forceinline__ unsigned packh2(float a, float b) {
    __half2 h = __floats2half2_rn(a, b);
    return *(unsigned*)&h;
}
__device__ __forceinline__ unsigned hmul2u(unsigned a, unsigned s) {
    __half2 r = __hmul2(*(__half2*)&a, *(__half2*)&s);
    return *(unsigned*)&r;
}

__device__ __forceinline__ void cp_async16(unsigned smem_addr, const void* gptr) {
    asm volatile("cp.async.cg.shared.global [%0], [%1], 16;" :: "r"(smem_addr), "l"(gptr));
}
__device__ __forceinline__ void cp_async16p(unsigned smem_addr, const void* gptr, int szbytes) {
    asm volatile("cp.async.cg.shared.global [%0], [%1], 16, %2;"
                 :: "r"(smem_addr), "l"(gptr), "r"(szbytes));
}
__device__ __forceinline__ void cp_commit() { asm volatile("cp.async.commit_group;"); }
__device__ __forceinline__ void cp_wait0() { asm volatile("cp.async.wait_group 0;"); }

__device__ __forceinline__ void ldsm_x4(unsigned& r0, unsigned& r1, unsigned& r2, unsigned& r3,
                                        unsigned addr) {
    asm volatile("ldmatrix.sync.aligned.m8n8.x4.shared.b16 {%0,%1,%2,%3}, [%4];"
                 : "=r"(r0), "=r"(r1), "=r"(r2), "=r"(r3) : "r"(addr));
}

#define MMA16816(acc, a0, a1, a2, a3, b0, b1) \
    asm volatile( \
        "mma.sync.aligned.m16n8k16.row.col.f32.f16.f16.f32 " \
        "{%0,%1,%2,%3}, {%4,%5,%6,%7}, {%8,%9}, {%0,%1,%2,%3};" \
        : "+f"((acc)[0]), "+f"((acc)[1]), "+f"((acc)[2]), "+f"((acc)[3]) \
        : "r"(a0), "r"(a1), "r"(a2), "r"(a3), "r"(b0), "r"(b1))

// ---------------- setup kernels ----------------
__global__ void k_zero() {
    int i = blockIdx.x * blockDim.x + threadIdx.x;
    if (i < NN) { g_deg[i] = 0; g_cursor[i] = 0; }
    if (i < NG) g_gcnt[i] = 0;
    if (i == 0) g_delta_acc = 0.f;
}

__global__ void k_hist(const int* __restrict__ ei, const int* __restrict__ batch) {
    int e = blockIdx.x * blockDim.x + threadIdx.x;
    if (e < NE) atomicAdd(&g_deg[ei[NE + e]], 1);     // dst row
    if (e < NN) atomicAdd(&g_gcnt[batch[e]], 1);
}

// scans rowptr + graph offsets; also computes delta (sum of log1p(deg))
__global__ void k_scan() {
    __shared__ int s[1024];
    __shared__ float fs[1024];
    int t = threadIdx.x;
    const int C = (NN + 1023) / 1024;
    int base = t * C;
    int acc = 0;
    float dl = 0.f;
    for (int c = 0; c < C; c++) {
        int i = base + c;
        if (i < NN) { int d = g_deg[i]; acc += d; dl += log1pf((float)d); }
    }
    s[t] = acc;
    fs[t] = dl;
    __syncthreads();
    for (int d = 1; d < 1024; d <<= 1) {
        int add = (t >= d) ? s[t - d] : 0;
        __syncthreads();
        s[t] += add;
        __syncthreads();
    }
    int off = s[t] - acc;
    for (int c = 0; c < C; c++) { int i = base + c; if (i < NN) { g_rowptr[i] = off; off += g_deg[i]; } }
    if (t == 0) g_rowptr[NN] = NE;
    // delta reduce
    for (int d = 512; d; d >>= 1) {
        __syncthreads();
        if (t < d) fs[t] += fs[t + d];
    }
    if (t == 0) g_delta_acc = fs[0];
    __syncthreads();
    int v = (t < NG) ? g_gcnt[t] : 0;
    s[t] = v;
    __syncthreads();
    for (int d = 1; d < 1024; d <<= 1) {
        int add = (t >= d) ? s[t - d] : 0;
        __syncthreads();
        s[t] += add;
        __syncthreads();
    }
    if (t < NG) g_goff[t] = s[t] - v;
    if (t == 0) g_goff[NG] = NN;
}

// scatter edges to CSR + per-node scalars (amp/att/dinv)
__global__ void k_scatter(const int* __restrict__ ei) {
    int e = blockIdx.x * blockDim.x + threadIdx.x;
    if (e < NN) {
        float deg = (float)g_deg[e];
        float d = fmaxf(deg, 1.f);
        float ld = log1pf(d);
        float delta = g_delta_acc / (float)NN;
        g_amp[e] = ld / delta;
        g_att[e] = delta / ld;
        g_dinv[e] = 1.f / d;
    }
    if (e >= NE) return;
    int dst = ei[NE + e];
    int p = atomicAdd(&g_cursor[dst], 1);
    g_srcperm[g_rowptr[dst] + p] = ei[e];
}

// merged: node embedding + weight transpose/convert
__global__ void k_prep(const float* __restrict__ x, const float* __restrict__ W,
                       const float* __restrict__ b, const float* __restrict__ conv_W) {
    int t = blockIdx.x * blockDim.x + threadIdx.x;
    if (t < NN * 32) {
        int i = t >> 5, c = t & 31;
        float x0 = x[i * 3 + 0], x1 = x[i * 3 + 1], x2 = x[i * 3 + 2];
        float4 w0 = *(const float4*)&W[0 * DD + c * 4];
        float4 w1 = *(const float4*)&W[1 * DD + c * 4];
        float4 w2 = *(const float4*)&W[2 * DD + c * 4];
        float4 bb = *(const float4*)&b[c * 4];
        float4 h;
        h.x = bb.x + x0 * w0.x + x1 * w1.x + x2 * w2.x;
        h.y = bb.y + x0 * w0.y + x1 * w1.y + x2 * w2.y;
        h.z = bb.z + x0 * w0.z + x1 * w1.z + x2 * w2.z;
        h.w = bb.w + x0 * w0.w + x1 * w1.w + x2 * w2.w;
        ((float4*)g_h)[i * 32 + c] = h;
        ((uint2*)g_hH)[i * 32 + c] = make_uint2(packh2(h.x, h.y), packh2(h.z, h.w));
    }
    if (t < NL * 1536 * DD) {
        int l = t / (1536 * DD);
        int r = t - l * (1536 * DD);
        int k = r >> 7;
        int n = r & 127;
        g_WtH[((size_t)l * DD + n) * 1536 + k] = __float2half_rn(conv_W[t]);
    }
}

// ---------------- per-layer kernels ----------------
// warp per node (R14 version); gathers fp16 h rows; writes UNSCALED fp16 aggs [N][512].
__global__ void k_agg() {
    if (blockIdx.x == 0 && threadIdx.x < DD) {    // reset BN accumulators for this layer
        g_bnsum[threadIdx.x] = 0.f;
        g_bnsq[threadIdx.x] = 0.f;
    }
    int warp = (blockIdx.x * blockDim.x + threadIdx.x) >> 5;
    int lane = threadIdx.x & 31;
    if (warp >= NN) return;
    int beg = g_rowptr[warp], end = g_rowptr[warp + 1];
    float4 s1 = f4zero(), s2 = f4zero();
    float4 mn = make_float4(INFINITY, INFINITY, INFINITY, INFINITY);
    float4 mx = make_float4(-INFINITY, -INFINITY, -INFINITY, -INFINITY);
    const uint2* hp = (const uint2*)g_hH;
    for (int e = beg; e < end; e += 32) {
        int myj = (e + lane < end) ? g_srcperm[e + lane] : 0;
        int cnt = min(32, end - e);
#pragma unroll 8
        for (int kk = 0; kk < cnt; kk++) {
            int j = __shfl_sync(0xffffffffu, myj, kk);
            uint2 v = hp[j * 32 + lane];
            float2 f01 = __half22float2(*(__half2*)&v.x);
            float2 f23 = __half22float2(*(__half2*)&v.y);
            float4 m = make_float4(f01.x, f01.y, f23.x, f23.y);
            s1.x += m.x; s1.y += m.y; s1.z += m.z; s1.w += m.w;
            s2.x += m.x * m.x; s2.y += m.y * m.y; s2.z += m.z * m.z; s2.w += m.w * m.w;
            mn.x = fminf(mn.x, m.x); mn.y = fminf(mn.y, m.y); mn.z = fminf(mn.z, m.z); mn.w = fminf(mn.w, m.w);
            mx.x = fmaxf(mx.x, m.x); mx.y = fmaxf(mx.y, m.y); mx.z = fmaxf(mx.z, m.z); mx.w = fmaxf(mx.w, m.w);
        }
    }
    float dinv = g_dinv[warp];
    float4 mean, sd;
    mean.x = s1.x * dinv; mean.y = s1.y * dinv; mean.z = s1.z * dinv; mean.w = s1.w * dinv;
    sd.x = sqrtf(fmaxf(s2.x * dinv - mean.x * mean.x, 0.f) + EPSF);
    sd.y = sqrtf(fmaxf(s2.y * dinv - mean.y * mean.y, 0.f) + EPSF);
    sd.z = sqrtf(fmaxf(s2.z * dinv - mean.z * mean.z, 0.f) + EPSF);
    sd.w = sqrtf(fmaxf(s2.w * dinv - mean.w * mean.w, 0.f) + EPSF);
    if (beg == end) { mn = f4zero(); mx = f4zero(); }

    float4 ag[4] = { mean, mn, mx, sd };
    unsigned* base = g_aggsH + (size_t)warp * 256;
#pragma unroll
    for (int a = 0; a < 4; a++) {
        uint2 w;
        w.x = packh2(ag[a].x, ag[a].y);
        w.y = packh2(ag[a].z, ag[a].w);
        *(uint2*)&base[a * 64 + lane * 2] = w;
    }
}

// ---------------- FP16 tensor-core GEMM with in-fragment slab scaling ----------------
// out = Σ_s (scale_s ⊙ A) @ W_s.  16 chunks of K=32; per chunk: 1 A tile + 3 B tiles.
#define BM 128
#define SW 20                          // 32-bit words per row (16 used + 4 pad)
#define NCH3 16                        // 512 / 32
#define TILE_B (BM * SW * 4)           // 10240 bytes per tile
#define STAGE_B (4 * TILE_B)           // A + 3 B
#define GM_DYN (2 * STAGE_B)           // 81920

__global__ __launch_bounds__(256, 2) void k_gemm(const __half* __restrict__ WtH,
                                                 const float* __restrict__ bl) {
    extern __shared__ unsigned dynS[];
    __shared__ float sBias[DD];
    __shared__ float sSum[DD], sSq[DD];
    __shared__ unsigned sAmp2[BM], sAtt2[BM];   // half2 broadcast per row

    int bm = blockIdx.x * BM;
    int tid = threadIdx.x;
    int lane = tid & 31;
    int warp = tid >> 5;
    int g = lane >> 2;
    int t = lane & 3;
    int m_base = (warp >> 2) * 64;
    int n_base = (warp & 3) * 32;

    if (tid < DD) {
        sBias[tid] = bl[tid];
        sSum[tid] = 0.f;
        sSq[tid] = 0.f;
        int r = bm + tid;
        float af = (r < NN) ? g_amp[r] : 1.f;
        float tf = (r < NN) ? g_att[r] : 1.f;
        sAmp2[tid] = packh2(af, af);
        sAtt2[tid] = packh2(tf, tf);
    }
    __syncthreads();

    float acc[4][4][4];
#pragma unroll
    for (int i = 0; i < 4; i++)
#pragma unroll
        for (int j = 0; j < 4; j++)
#pragma unroll
            for (int c = 0; c < 4; c++) acc[i][j][c] = 0.f;

    const int cpRow = tid >> 2;
    const int cpSeg = tid & 3;
    const int row2 = cpRow + 64;

    const unsigned base = (unsigned)__cvta_generic_to_shared(&dynS[0]);

    auto cpAB = [&](int chunk, int buf) {
        unsigned st = base + buf * STAGE_B;
#pragma unroll
        for (int u = 0; u < 2; u++) {
            int row = u ? row2 : cpRow;
            unsigned dst = (unsigned)(row * SW + cpSeg * 4) * 4u;
            const unsigned* pa = g_aggsH + (size_t)(bm + row) * 256 + chunk * 16 + cpSeg * 4;
            cp_async16p(st + dst, pa, (bm + row) < NN ? 16 : 0);
#pragma unroll
            for (int s = 0; s < 3; s++)
                cp_async16(st + (1 + s) * TILE_B + dst,
                           WtH + (size_t)row * 1536 + s * 512 + chunk * 32 + cpSeg * 8);
        }
    };

    const int l8 = lane & 7;
    const unsigned aLane = (unsigned)((l8 + ((lane >> 3) & 1) * 8) * SW * 4 + ((lane >> 4) & 1) * 16);
    const unsigned bLane = (unsigned)((l8 + ((lane >> 4) & 1) * 8) * SW * 4 + ((lane >> 3) & 1) * 16);

    auto mmaChunk = [&](int buf) {
        unsigned st = base + buf * STAGE_B;
        unsigned aB = st + (unsigned)(m_base * SW * 4) + aLane;
        unsigned bB = st + TILE_B + (unsigned)(n_base * SW * 4) + bLane;
#pragma unroll
        for (int ks = 0; ks < 2; ks++) {
            unsigned bf[3][4][2];
#pragma unroll
            for (int s = 0; s < 3; s++) {
                unsigned bb = bB + s * TILE_B;
                ldsm_x4(bf[s][0][0], bf[s][0][1], bf[s][1][0], bf[s][1][1], bb + ks * 32);
                ldsm_x4(bf[s][2][0], bf[s][2][1], bf[s][3][0], bf[s][3][1], bb + 16 * SW * 4 + ks * 32);
            }
#pragma unroll
            for (int i = 0; i < 4; i++) {
                unsigned a0, a1, a2, a3;
                ldsm_x4(a0, a1, a2, a3, aB + (unsigned)(i * 16 * SW * 4) + ks * 32);
#pragma unroll
                for (int j = 0; j < 4; j++)
                    MMA16816(acc[i][j], a0, a1, a2, a3, bf[0][j][0], bf[0][j][1]);
                int rl = m_base + i * 16 + g;
                {
                    unsigned sl = sAmp2[rl], sh = sAmp2[rl + 8];
                    unsigned u0 = hmul2u(a0, sl), u1 = hmul2u(a1, sh);
                    unsigned u2 = hmul2u(a2, sl), u3 = hmul2u(a3, sh);
#pragma unroll
                    for (int j = 0; j < 4; j++)
                        MMA16816(acc[i][j], u0, u1, u2, u3, bf[1][j][0], bf[1][j][1]);
                }
                {
                    unsigned sl = sAtt2[rl], sh = sAtt2[rl + 8];
                    unsigned u0 = hmul2u(a0, sl), u1 = hmul2u(a1, sh);
                    unsigned u2 = hmul2u(a2, sl), u3 = hmul2u(a3, sh);
#pragma unroll
                    for (int j = 0; j < 4; j++)
                        MMA16816(acc[i][j], u0, u1, u2, u3, bf[2][j][0], bf[2][j][1]);
                }
            }
        }
    };

    cpAB(0, 0);
    cp_commit();

    for (int c = 0; c < NCH3; c++) {
        cp_wait0();
        __syncthreads();
        if (c + 1 < NCH3) {
            cpAB(c + 1, (c + 1) & 1);
            cp_commit();
        }
        mmaChunk(c & 1);
    }

    // epilogue: bias + store
#pragma unroll
    for (int i = 0; i < 4; i++) {
        int r0 = bm + m_base + i * 16 + g;
        int r1 = r0 + 8;
#pragma unroll
        for (int j = 0; j < 4; j++) {
            int col = n_base + j * 8 + t * 2;
            float bx = sBias[col], by = sBias[col + 1];
            acc[i][j][0] += bx; acc[i][j][1] += by;
            acc[i][j][2] += bx; acc[i][j][3] += by;
            if (r0 < NN)
                *(float2*)&g_out[(size_t)r0 * DD + col] = make_float2(acc[i][j][0], acc[i][j][1]);
            if (r1 < NN)
                *(float2*)&g_out[(size_t)r1 * DD + col] = make_float2(acc[i][j][2], acc[i][j][3]);
        }
    }

    // fused BN stats
#pragma unroll
    for (int j = 0; j < 4; j++)
#pragma unroll
        for (int c2 = 0; c2 < 2; c2++) {
            int col = n_base + j * 8 + t * 2 + c2;
            float s = 0.f, q = 0.f;
#pragma unroll
            for (int i = 0; i < 4; i++) {
                int r0 = bm + m_base + i * 16 + g;
                float v0 = acc[i][j][c2];
                float v1 = acc[i][j][2 + c2];
                if (r0 < NN) { s += v0; q += v0 * v0; }
                if (r0 + 8 < NN) { s += v1; q += v1 * v1; }
            }
#pragma unroll
            for (int m = 4; m <= 16; m <<= 1) {
                s += __shfl_xor_sync(0xffffffffu, s, m);
                q += __shfl_xor_sync(0xffffffffu, q, m);
            }
            if (g == 0) {
                atomicAdd(&sSum[col], s);
                atomicAdd(&sSq[col], q);
            }
        }
    __syncthreads();
    if (tid < DD) {
        atomicAdd(&g_bnsum[tid], sSum[tid]);
        atomicAdd(&g_bnsq[tid], sSq[tid]);
    }
}

// BN apply with inline param computation + residual; optional fp16 mirror
__global__ void k_bnapply(const float* __restrict__ gamma, const float* __restrict__ beta,
                          int mirror) {
    int t = blockIdx.x * blockDim.x + threadIdx.x;
    if (t >= NN * 32) return;
    int c = (t & 31) * 4;
    float mu[4], rsg[4], bt[4];
#pragma unroll
    for (int u = 0; u < 4; u++) {
        float m = g_bnsum[c + u] / (float)NN;
        float var = g_bnsq[c + u] / (float)NN - m * m;
        mu[u] = m;
        rsg[u] = rsqrtf(var + EPSF) * gamma[c + u];
        bt[u] = beta[c + u];
    }
    float4 o = ((const float4*)g_out)[t];
    float4 h = ((float4*)g_h)[t];
    o.x = fmaxf((o.x - mu[0]) * rsg[0] + bt[0], 0.f) + h.x;
    o.y = fmaxf((o.y - mu[1]) * rsg[1] + bt[1], 0.f) + h.y;
    o.z = fmaxf((o.z - mu[2]) * rsg[2] + bt[2], 0.f) + h.z;
    o.w = fmaxf((o.w - mu[3]) * rsg[3] + bt[3], 0.f) + h.w;
    ((float4*)g_h)[t] = o;
    if (mirror)
        ((uint2*)g_hH)[t] = make_uint2(packh2(o.x, o.y), packh2(o.z, o.w));
}

// ---------------- fused pooling + MLP: one block per graph ----------------
__global__ void k_poolmlp(const float* __restrict__ W1, const float* __restrict__ b1,
                          const float* __restrict__ W2, const float* __restrict__ b2,
                          const float* __restrict__ W3, const float* __restrict__ b3,
                          float* __restrict__ out) {
    __shared__ float sg[DD], sz1[64], sz2[32];
    int gid = blockIdx.x;
    int tid = threadIdx.x;      // 128 threads, one per feature
    int beg = g_goff[gid], end = g_goff[gid + 1];
    float s = 0.f;
    for (int r = beg; r < end; r++) s += g_h[(size_t)r * DD + tid];
    sg[tid] = s / (float)max(end - beg, 1);
    __syncthreads();
    if (tid < 64) {
        float a = b1[tid];
        for (int k = 0; k < DD; k++) a += sg[k] * W1[k * 64 + tid];
        sz1[tid] = fmaxf(a, 0.f);
    }
    __syncthreads();
    if (tid < 32) {
        float a = b2[tid];
        for (int k = 0; k < 64; k++) a += sz1[k] * W2[k * 32 + tid];
        sz2[tid] = fmaxf(a, 0.f);
    }
    __syncthreads();
    if (tid < NT) {
        float a = b3[tid];
        for (int k = 0; k < 32; k++) a += sz2[k] * W3[k * NT + tid];
        out[gid * NT + tid] = a;
    }
}

// ---------------- launch ----------------
extern "C" void kernel_launch(void* const* d_in, const int* in_sizes, int n_in,
                              void* d_out, int out_size) {
    const float* x      = (const float*)d_in[0];
    const int*   ei     = (const int*)d_in[1];
    const int*   batch  = (const int*)d_in[2];
    const float* emb_W  = (const float*)d_in[3];
    const float* emb_b  = (const float*)d_in[4];
    const float* conv_W = (const float*)d_in[5];
    const float* conv_b = (const float*)d_in[6];
    const float* bng    = (const float*)d_in[7];
    const float* bnb    = (const float*)d_in[8];
    const float* W1     = (const float*)d_in[9];
    const float* b1     = (const float*)d_in[10];
    const float* W2     = (const float*)d_in[11];
    const float* b2     = (const float*)d_in[12];
    const float* W3     = (const float*)d_in[13];
    const float* b3     = (const float*)d_in[14];
    float* out = (float*)d_out;

    cudaFuncSetAttribute(k_gemm, cudaFuncAttributeMaxDynamicSharedMemorySize, GM_DYN);

    k_zero<<<(NN + 255) / 256, 256>>>();
    k_hist<<<(NE + 255) / 256, 256>>>(ei, batch);
    k_scan<<<1, 1024>>>();
    k_scatter<<<(NE + 255) / 256, 256>>>(ei);
    k_prep<<<(NN * 32 + 255) / 256, 256>>>(x, emb_W, emb_b, conv_W);

    __half* g_WtH_ptr;
    cudaGetSymbolAddress((void**)&g_WtH_ptr, g_WtH);

    for (int l = 0; l < NL; l++) {
        k_agg<<<(NN * 32 + 255) / 256, 256>>>();
        k_gemm<<<(NN + BM - 1) / BM, 256, GM_DYN>>>(g_WtH_ptr + (size_t)l * DD * 1536,
                                                    conv_b + (size_t)l * DD);
        k_bnapply<<<(NN * 32 + 255) / 256, 256>>>(bng + (size_t)l * DD, bnb + (size_t)l * DD,
                                                  l < NL - 1);
    }

    k_poolmlp<<<NG, DD>>>(W1, b1, W2, b2, W3, b3, out);
}

// round 17
// speedup vs baseline: 1.0710x; 1.0090x over previous
#include <cuda_runtime.h>
#include <cuda_fp16.h>
#include <math.h>

#define NN 50000
#define NE 600000
#define DD 128
#define NL 4
#define NG 512
#define NT 10
#define EPSF 1e-5f

// ---------------- scratch (static device allocations) ----------------
__device__ int   g_deg[NN];
__device__ int   g_rowptr[NN + 1];
__device__ int   g_cursor[NN];
__device__ int   g_srcperm[NE];
__device__ float g_amp[NN], g_att[NN], g_dinv[NN];
__device__ float g_delta_acc;
__device__ float g_h[NN * DD];
__device__ unsigned g_hH[NN * DD / 2];              // fp16 mirror of g_h (packed half2)
__device__ unsigned g_aggsH[(size_t)NN * 256];      // [N][512] halves: unscaled mean|min|max|std
__device__ float g_out[NN * DD];
__device__ float g_bnsum[DD], g_bnsq[DD];
__device__ int   g_gcnt[NG];
__device__ int   g_goff[NG + 1];
__device__ __half g_WtH[(size_t)NL * DD * 1536];    // W transposed fp16: [l][n][k]

// ---------------- small helpers ----------------
__device__ __forceinline__ float4 f4zero() { return make_float4(0.f, 0.f, 0.f, 0.f); }

__device__ __forceinline__ unsigned packh2(float a, float b) {
    __half2 h = __floats2half2_rn(a, b);
    return *(unsigned*)&h;
}
__device__ __forceinline__ unsigned hmul2u(unsigned a, unsigned s) {
    __half2 r = __hmul2(*(__half2*)&a, *(__half2*)&s);
    return *(unsigned*)&r;
}

__device__ __forceinline__ void cp_async16(unsigned smem_addr, const void* gptr) {
    asm volatile("cp.async.cg.shared.global [%0], [%1], 16;" :: "r"(smem_addr), "l"(gptr));
}
__device__ __forceinline__ void cp_async16p(unsigned smem_addr, const void* gptr, int szbytes) {
    asm volatile("cp.async.cg.shared.global [%0], [%1], 16, %2;"
                 :: "r"(smem_addr), "l"(gptr), "r"(szbytes));
}
__device__ __forceinline__ void cp_commit() { asm volatile("cp.async.commit_group;"); }
__device__ __forceinline__ void cp_wait0() { asm volatile("cp.async.wait_group 0;"); }

__device__ __forceinline__ void ldsm_x4(unsigned& r0, unsigned& r1, unsigned& r2, unsigned& r3,
                                        unsigned addr) {
    asm volatile("ldmatrix.sync.aligned.m8n8.x4.shared.b16 {%0,%1,%2,%3}, [%4];"
                 : "=r"(r0), "=r"(r1), "=r"(r2), "=r"(r3) : "r"(addr));
}

#define MMA16816(acc, a0, a1, a2, a3, b0, b1) \
    asm volatile( \
        "mma.sync.aligned.m16n8k16.row.col.f32.f16.f16.f32 " \
        "{%0,%1,%2,%3}, {%4,%5,%6,%7}, {%8,%9}, {%0,%1,%2,%3};" \
        : "+f"((acc)[0]), "+f"((acc)[1]), "+f"((acc)[2]), "+f"((acc)[3]) \
        : "r"(a0), "r"(a1), "r"(a2), "r"(a3), "r"(b0), "r"(b1))

// ---------------- setup kernels ----------------
__global__ void k_zero() {
    int i = blockIdx.x * blockDim.x + threadIdx.x;
    if (i < NN) { g_deg[i] = 0; g_cursor[i] = 0; }
    if (i < NG) g_gcnt[i] = 0;
    if (i == 0) g_delta_acc = 0.f;
}

__global__ void k_hist(const int* __restrict__ ei, const int* __restrict__ batch) {
    int e = blockIdx.x * blockDim.x + threadIdx.x;
    if (e < NE) atomicAdd(&g_deg[ei[NE + e]], 1);     // dst row
    if (e < NN) atomicAdd(&g_gcnt[batch[e]], 1);
}

// scans rowptr + graph offsets; also computes delta (sum of log1p(deg))
__global__ void k_scan() {
    __shared__ int s[1024];
    __shared__ float fs[1024];
    int t = threadIdx.x;
    const int C = (NN + 1023) / 1024;
    int base = t * C;
    int acc = 0;
    float dl = 0.f;
    for (int c = 0; c < C; c++) {
        int i = base + c;
        if (i < NN) { int d = g_deg[i]; acc += d; dl += log1pf((float)d); }
    }
    s[t] = acc;
    fs[t] = dl;
    __syncthreads();
    for (int d = 1; d < 1024; d <<= 1) {
        int add = (t >= d) ? s[t - d] : 0;
        __syncthreads();
        s[t] += add;
        __syncthreads();
    }
    int off = s[t] - acc;
    for (int c = 0; c < C; c++) { int i = base + c; if (i < NN) { g_rowptr[i] = off; off += g_deg[i]; } }
    if (t == 0) g_rowptr[NN] = NE;
    // delta reduce
    for (int d = 512; d; d >>= 1) {
        __syncthreads();
        if (t < d) fs[t] += fs[t + d];
    }
    if (t == 0) g_delta_acc = fs[0];
    __syncthreads();
    int v = (t < NG) ? g_gcnt[t] : 0;
    s[t] = v;
    __syncthreads();
    for (int d = 1; d < 1024; d <<= 1) {
        int add = (t >= d) ? s[t - d] : 0;
        __syncthreads();
        s[t] += add;
        __syncthreads();
    }
    if (t < NG) g_goff[t] = s[t] - v;
    if (t == 0) g_goff[NG] = NN;
}

// scatter edges to CSR + per-node scalars (amp/att/dinv)
__global__ void k_scatter(const int* __restrict__ ei) {
    int e = blockIdx.x * blockDim.x + threadIdx.x;
    if (e < NN) {
        float deg = (float)g_deg[e];
        float d = fmaxf(deg, 1.f);
        float ld = log1pf(d);
        float delta = g_delta_acc / (float)NN;
        g_amp[e] = ld / delta;
        g_att[e] = delta / ld;
        g_dinv[e] = 1.f / d;
    }
    if (e >= NE) return;
    int dst = ei[NE + e];
    int p = atomicAdd(&g_cursor[dst], 1);
    g_srcperm[g_rowptr[dst] + p] = ei[e];
}

// merged: node embedding + weight transpose/convert
__global__ void k_prep(const float* __restrict__ x, const float* __restrict__ W,
                       const float* __restrict__ b, const float* __restrict__ conv_W) {
    int t = blockIdx.x * blockDim.x + threadIdx.x;
    if (t < NN * 32) {
        int i = t >> 5, c = t & 31;
        float x0 = x[i * 3 + 0], x1 = x[i * 3 + 1], x2 = x[i * 3 + 2];
        float4 w0 = *(const float4*)&W[0 * DD + c * 4];
        float4 w1 = *(const float4*)&W[1 * DD + c * 4];
        float4 w2 = *(const float4*)&W[2 * DD + c * 4];
        float4 bb = *(const float4*)&b[c * 4];
        float4 h;
        h.x = bb.x + x0 * w0.x + x1 * w1.x + x2 * w2.x;
        h.y = bb.y + x0 * w0.y + x1 * w1.y + x2 * w2.y;
        h.z = bb.z + x0 * w0.z + x1 * w1.z + x2 * w2.z;
        h.w = bb.w + x0 * w0.w + x1 * w1.w + x2 * w2.w;
        ((float4*)g_h)[i * 32 + c] = h;
        ((uint2*)g_hH)[i * 32 + c] = make_uint2(packh2(h.x, h.y), packh2(h.z, h.w));
    }
    if (t < NL * 1536 * DD) {
        int l = t / (1536 * DD);
        int r = t - l * (1536 * DD);
        int k = r >> 7;
        int n = r & 127;
        g_WtH[((size_t)l * DD + n) * 1536 + k] = __float2half_rn(conv_W[t]);
    }
}

// ---------------- per-layer kernels ----------------
// warp per node; gathers fp16 h rows; half2 min/max (exact), fp32 sum/sumsq.
__global__ void k_agg() {
    if (blockIdx.x == 0 && threadIdx.x < DD) {    // reset BN accumulators for this layer
        g_bnsum[threadIdx.x] = 0.f;
        g_bnsq[threadIdx.x] = 0.f;
    }
    int warp = (blockIdx.x * blockDim.x + threadIdx.x) >> 5;
    int lane = threadIdx.x & 31;
    if (warp >= NN) return;
    int beg = g_rowptr[warp], end = g_rowptr[warp + 1];
    float4 s1 = f4zero(), s2 = f4zero();
    __half2 mn0 = __float2half2_rn(65504.f),  mn1 = __float2half2_rn(65504.f);
    __half2 mx0 = __float2half2_rn(-65504.f), mx1 = __float2half2_rn(-65504.f);
    const uint2* hp = (const uint2*)g_hH;
    for (int e = beg; e < end; e += 32) {
        int myj = (e + lane < end) ? g_srcperm[e + lane] : 0;
        int cnt = min(32, end - e);
#pragma unroll 8
        for (int kk = 0; kk < cnt; kk++) {
            int j = __shfl_sync(0xffffffffu, myj, kk);
            uint2 v = hp[j * 32 + lane];
            __half2 h0 = *(__half2*)&v.x;
            __half2 h1 = *(__half2*)&v.y;
            float2 f01 = __half22float2(h0);
            float2 f23 = __half22float2(h1);
            s1.x += f01.x; s1.y += f01.y; s1.z += f23.x; s1.w += f23.y;
            s2.x += f01.x * f01.x; s2.y += f01.y * f01.y;
            s2.z += f23.x * f23.x; s2.w += f23.y * f23.y;
            mn0 = __hmin2(mn0, h0); mn1 = __hmin2(mn1, h1);
            mx0 = __hmax2(mx0, h0); mx1 = __hmax2(mx1, h1);
        }
    }
    float dinv = g_dinv[warp];
    float4 mean, sd;
    mean.x = s1.x * dinv; mean.y = s1.y * dinv; mean.z = s1.z * dinv; mean.w = s1.w * dinv;
    sd.x = sqrtf(fmaxf(s2.x * dinv - mean.x * mean.x, 0.f) + EPSF);
    sd.y = sqrtf(fmaxf(s2.y * dinv - mean.y * mean.y, 0.f) + EPSF);
    sd.z = sqrtf(fmaxf(s2.z * dinv - mean.z * mean.z, 0.f) + EPSF);
    sd.w = sqrtf(fmaxf(s2.w * dinv - mean.w * mean.w, 0.f) + EPSF);
    if (beg == end) {
        mn0 = __float2half2_rn(0.f); mn1 = __float2half2_rn(0.f);
        mx0 = __float2half2_rn(0.f); mx1 = __float2half2_rn(0.f);
    }

    unsigned* base = g_aggsH + (size_t)warp * 256;
    uint2 w;
    w.x = packh2(mean.x, mean.y); w.y = packh2(mean.z, mean.w);
    *(uint2*)&base[0 * 64 + lane * 2] = w;
    w.x = *(unsigned*)&mn0; w.y = *(unsigned*)&mn1;
    *(uint2*)&base[1 * 64 + lane * 2] = w;
    w.x = *(unsigned*)&mx0; w.y = *(unsigned*)&mx1;
    *(uint2*)&base[2 * 64 + lane * 2] = w;
    w.x = packh2(sd.x, sd.y); w.y = packh2(sd.z, sd.w);
    *(uint2*)&base[3 * 64 + lane * 2] = w;
}

// ---------------- FP16 tensor-core GEMM with in-fragment slab scaling ----------------
// out = Σ_s (scale_s ⊙ A) @ W_s.  16 chunks of K=32; per chunk: 1 A tile + 3 B tiles.
#define BM 128
#define SW 20                          // 32-bit words per row (16 used + 4 pad)
#define NCH3 16                        // 512 / 32
#define TILE_B (BM * SW * 4)           // 10240 bytes per tile
#define STAGE_B (4 * TILE_B)           // A + 3 B
#define GM_DYN (2 * STAGE_B)           // 81920

__global__ __launch_bounds__(256, 2) void k_gemm(const __half* __restrict__ WtH,
                                                 const float* __restrict__ bl) {
    extern __shared__ unsigned dynS[];
    __shared__ float sBias[DD];
    __shared__ float sSum[DD], sSq[DD];
    __shared__ unsigned sAmp2[BM], sAtt2[BM];   // half2 broadcast per row

    int bm = blockIdx.x * BM;
    int tid = threadIdx.x;
    int lane = tid & 31;
    int warp = tid >> 5;
    int g = lane >> 2;
    int t = lane & 3;
    int m_base = (warp >> 2) * 64;
    int n_base = (warp & 3) * 32;

    if (tid < DD) {
        sBias[tid] = bl[tid];
        sSum[tid] = 0.f;
        sSq[tid] = 0.f;
        int r = bm + tid;
        float af = (r < NN) ? g_amp[r] : 1.f;
        float tf = (r < NN) ? g_att[r] : 1.f;
        sAmp2[tid] = packh2(af, af);
        sAtt2[tid] = packh2(tf, tf);
    }
    __syncthreads();

    float acc[4][4][4];
#pragma unroll
    for (int i = 0; i < 4; i++)
#pragma unroll
        for (int j = 0; j < 4; j++)
#pragma unroll
            for (int c = 0; c < 4; c++) acc[i][j][c] = 0.f;

    const int cpRow = tid >> 2;
    const int cpSeg = tid & 3;
    const int row2 = cpRow + 64;

    const unsigned base = (unsigned)__cvta_generic_to_shared(&dynS[0]);

    auto cpAB = [&](int chunk, int buf) {
        unsigned st = base + buf * STAGE_B;
#pragma unroll
        for (int u = 0; u < 2; u++) {
            int row = u ? row2 : cpRow;
            unsigned dst = (unsigned)(row * SW + cpSeg * 4) * 4u;
            const unsigned* pa = g_aggsH + (size_t)(bm + row) * 256 + chunk * 16 + cpSeg * 4;
            cp_async16p(st + dst, pa, (bm + row) < NN ? 16 : 0);
#pragma unroll
            for (int s = 0; s < 3; s++)
                cp_async16(st + (1 + s) * TILE_B + dst,
                           WtH + (size_t)row * 1536 + s * 512 + chunk * 32 + cpSeg * 8);
        }
    };

    const int l8 = lane & 7;
    const unsigned aLane = (unsigned)((l8 + ((lane >> 3) & 1) * 8) * SW * 4 + ((lane >> 4) & 1) * 16);
    const unsigned bLane = (unsigned)((l8 + ((lane >> 4) & 1) * 8) * SW * 4 + ((lane >> 3) & 1) * 16);

    auto mmaChunk = [&](int buf) {
        unsigned st = base + buf * STAGE_B;
        unsigned aB = st + (unsigned)(m_base * SW * 4) + aLane;
        unsigned bB = st + TILE_B + (unsigned)(n_base * SW * 4) + bLane;
#pragma unroll
        for (int ks = 0; ks < 2; ks++) {
            unsigned bf[3][4][2];
#pragma unroll
            for (int s = 0; s < 3; s++) {
                unsigned bb = bB + s * TILE_B;
                ldsm_x4(bf[s][0][0], bf[s][0][1], bf[s][1][0], bf[s][1][1], bb + ks * 32);
                ldsm_x4(bf[s][2][0], bf[s][2][1], bf[s][3][0], bf[s][3][1], bb + 16 * SW * 4 + ks * 32);
            }
#pragma unroll
            for (int i = 0; i < 4; i++) {
                unsigned a0, a1, a2, a3;
                ldsm_x4(a0, a1, a2, a3, aB + (unsigned)(i * 16 * SW * 4) + ks * 32);
#pragma unroll
                for (int j = 0; j < 4; j++)
                    MMA16816(acc[i][j], a0, a1, a2, a3, bf[0][j][0], bf[0][j][1]);
                int rl = m_base + i * 16 + g;
                {
                    unsigned sl = sAmp2[rl], sh = sAmp2[rl + 8];
                    unsigned u0 = hmul2u(a0, sl), u1 = hmul2u(a1, sh);
                    unsigned u2 = hmul2u(a2, sl), u3 = hmul2u(a3, sh);
#pragma unroll
                    for (int j = 0; j < 4; j++)
                        MMA16816(acc[i][j], u0, u1, u2, u3, bf[1][j][0], bf[1][j][1]);
                }
                {
                    unsigned sl = sAtt2[rl], sh = sAtt2[rl + 8];
                    unsigned u0 = hmul2u(a0, sl), u1 = hmul2u(a1, sh);
                    unsigned u2 = hmul2u(a2, sl), u3 = hmul2u(a3, sh);
#pragma unroll
                    for (int j = 0; j < 4; j++)
                        MMA16816(acc[i][j], u0, u1, u2, u3, bf[2][j][0], bf[2][j][1]);
                }
            }
        }
    };

    cpAB(0, 0);
    cp_commit();

    for (int c = 0; c < NCH3; c++) {
        cp_wait0();
        __syncthreads();
        if (c + 1 < NCH3) {
            cpAB(c + 1, (c + 1) & 1);
            cp_commit();
        }
        mmaChunk(c & 1);
    }

    // epilogue: bias + store
#pragma unroll
    for (int i = 0; i < 4; i++) {
        int r0 = bm + m_base + i * 16 + g;
        int r1 = r0 + 8;
#pragma unroll
        for (int j = 0; j < 4; j++) {
            int col = n_base + j * 8 + t * 2;
            float bx = sBias[col], by = sBias[col + 1];
            acc[i][j][0] += bx; acc[i][j][1] += by;
            acc[i][j][2] += bx; acc[i][j][3] += by;
            if (r0 < NN)
                *(float2*)&g_out[(size_t)r0 * DD + col] = make_float2(acc[i][j][0], acc[i][j][1]);
            if (r1 < NN)
                *(float2*)&g_out[(size_t)r1 * DD + col] = make_float2(acc[i][j][2], acc[i][j][3]);
        }
    }

    // fused BN stats
#pragma unroll
    for (int j = 0; j < 4; j++)
#pragma unroll
        for (int c2 = 0; c2 < 2; c2++) {
            int col = n_base + j * 8 + t * 2 + c2;
            float s = 0.f, q = 0.f;
#pragma unroll
            for (int i = 0; i < 4; i++) {
                int r0 = bm + m_base + i * 16 + g;
                float v0 = acc[i][j][c2];
                float v1 = acc[i][j][2 + c2];
                if (r0 < NN) { s += v0; q += v0 * v0; }
                if (r0 + 8 < NN) { s += v1; q += v1 * v1; }
            }
#pragma unroll
            for (int m = 4; m <= 16; m <<= 1) {
                s += __shfl_xor_sync(0xffffffffu, s, m);
                q += __shfl_xor_sync(0xffffffffu, q, m);
            }
            if (g == 0) {
                atomicAdd(&sSum[col], s);
                atomicAdd(&sSq[col], q);
            }
        }
    __syncthreads();
    if (tid < DD) {
        atomicAdd(&g_bnsum[tid], sSum[tid]);
        atomicAdd(&g_bnsq[tid], sSq[tid]);
    }
}

// BN apply with inline param computation + residual; optional fp16 mirror
__global__ void k_bnapply(const float* __restrict__ gamma, const float* __restrict__ beta,
                          int mirror) {
    int t = blockIdx.x * blockDim.x + threadIdx.x;
    if (t >= NN * 32) return;
    int c = (t & 31) * 4;
    float mu[4], rsg[4], bt[4];
#pragma unroll
    for (int u = 0; u < 4; u++) {
        float m = g_bnsum[c + u] / (float)NN;
        float var = g_bnsq[c + u] / (float)NN - m * m;
        mu[u] = m;
        rsg[u] = rsqrtf(var + EPSF) * gamma[c + u];
        bt[u] = beta[c + u];
    }
    float4 o = ((const float4*)g_out)[t];
    float4 h = ((float4*)g_h)[t];
    o.x = fmaxf((o.x - mu[0]) * rsg[0] + bt[0], 0.f) + h.x;
    o.y = fmaxf((o.y - mu[1]) * rsg[1] + bt[1], 0.f) + h.y;
    o.z = fmaxf((o.z - mu[2]) * rsg[2] + bt[2], 0.f) + h.z;
    o.w = fmaxf((o.w - mu[3]) * rsg[3] + bt[3], 0.f) + h.w;
    ((float4*)g_h)[t] = o;
    if (mirror)
        ((uint2*)g_hH)[t] = make_uint2(packh2(o.x, o.y), packh2(o.z, o.w));
}

// ---------------- fused pooling + MLP: one block per graph ----------------
__global__ void k_poolmlp(const float* __restrict__ W1, const float* __restrict__ b1,
                          const float* __restrict__ W2, const float* __restrict__ b2,
                          const float* __restrict__ W3, const float* __restrict__ b3,
                          float* __restrict__ out) {
    __shared__ float sg[DD], sz1[64], sz2[32];
    int gid = blockIdx.x;
    int tid = threadIdx.x;      // 128 threads, one per feature
    int beg = g_goff[gid], end = g_goff[gid + 1];
    float s = 0.f;
    for (int r = beg; r < end; r++) s += g_h[(size_t)r * DD + tid];
    sg[tid] = s / (float)max(end - beg, 1);
    __syncthreads();
    if (tid < 64) {
        float a = b1[tid];
        for (int k = 0; k < DD; k++) a += sg[k] * W1[k * 64 + tid];
        sz1[tid] = fmaxf(a, 0.f);
    }
    __syncthreads();
    if (tid < 32) {
        float a = b2[tid];
        for (int k = 0; k < 64; k++) a += sz1[k] * W2[k * 32 + tid];
        sz2[tid] = fmaxf(a, 0.f);
    }
    __syncthreads();
    if (tid < NT) {
        float a = b3[tid];
        for (int k = 0; k < 32; k++) a += sz2[k] * W3[k * NT + tid];
        out[gid * NT + tid] = a;
    }
}

// ---------------- launch ----------------
extern "C" void kernel_launch(void* const* d_in, const int* in_sizes, int n_in,
                              void* d_out, int out_size) {
    const float* x      = (const float*)d_in[0];
    const int*   ei     = (const int*)d_in[1];
    const int*   batch  = (const int*)d_in[2];
    const float* emb_W  = (const float*)d_in[3];
    const float* emb_b  = (const float*)d_in[4];
    const float* conv_W = (const float*)d_in[5];
    const float* conv_b = (const float*)d_in[6];
    const float* bng    = (const float*)d_in[7];
    const float* bnb    = (const float*)d_in[8];
    const float* W1     = (const float*)d_in[9];
    const float* b1     = (const float*)d_in[10];
    const float* W2     = (const float*)d_in[11];
    const float* b2     = (const float*)d_in[12];
    const float* W3     = (const float*)d_in[13];
    const float* b3     = (const float*)d_in[14];
    float* out = (float*)d_out;

    cudaFuncSetAttribute(k_gemm, cudaFuncAttributeMaxDynamicSharedMemorySize, GM_DYN);

    k_zero<<<(NN + 255) / 256, 256>>>();
    k_hist<<<(NE + 255) / 256, 256>>>(ei, batch);
    k_scan<<<1, 1024>>>();
    k_scatter<<<(NE + 255) / 256, 256>>>(ei);
    k_prep<<<(NN * 32 + 255) / 256, 256>>>(x, emb_W, emb_b, conv_W);

    __half* g_WtH_ptr;
    cudaGetSymbolAddress((void**)&g_WtH_ptr, g_WtH);

    for (int l = 0; l < NL; l++) {
        k_agg<<<(NN * 32 + 255) / 256, 256>>>();
        k_gemm<<<(NN + BM - 1) / BM, 256, GM_DYN>>>(g_WtH_ptr + (size_t)l * DD * 1536,
                                                    conv_b + (size_t)l * DD);
        k_bnapply<<<(NN * 32 + 255) / 256, 256>>>(bng + (size_t)l * DD, bnb + (size_t)l * DD,
                                                  l < NL - 1);
    }

    k_poolmlp<<<NG, DD>>>(W1, b1, W2, b2, W3, b3, out);
}